// round 12
// baseline (speedup 1.0000x reference)
#include <cuda_runtime.h>
#include <cstdint>
#include <math.h>

#define BB   256
#define NNE  65536
#define H1BINS 4096   // 12-bit level-1 on r-keys
#define TIE_CAP 4096

// ---------------- scratch (static device globals; no allocation) ----------------
__device__ unsigned short g_b16[(size_t)BB * NNE];   // 32 MB: top 16 bits of r-key
__device__ unsigned g_cand[(size_t)BB * NNE];        // 64 MB: (b16<<16)|idx band candidates
__device__ uint2    g_cand2[(size_t)BB * NNE];       // 128 MB: (exact wkey, idx)
__device__ unsigned g_hist1[BB * H1BINS];            // 4 MB : level-1 histograms
__device__ unsigned g_p1k[BB];    // b16 >= this  <=>  strictly above selected bin
__device__ unsigned g_klo[BB], g_khi[BB];            // inclusive b16 candidate band
__device__ int      g_rem[BB];
__device__ int      g_ccnt[BB];
__device__ int      g_tickK[BB];  // keys-phase ticket (8 blocks/row)
__device__ int      g_tickS[BB];  // scan-phase ticket (16 blocks/row)

// ---------------- helpers ----------------
__device__ __forceinline__ unsigned float_key(float w) {
    unsigned x = __float_as_uint(w);
    return x ^ ((unsigned)((int)x >> 31) | 0x80000000u);   // order-preserving
}
__device__ __forceinline__ float key_to_float(unsigned key) {
    unsigned x = (key & 0x80000000u) ? (key ^ 0x80000000u) : ~key;
    return __uint_as_float(x);
}

// exact key: matches the reference's float32 op-order bit-for-bit (libdevice logf)
__device__ __forceinline__ unsigned weight_key_exact(float u, float d) {
    float l1 = logf(u + 1e-7f);
    float inner = -l1 + 1e-7f;
    float G = -logf(inner);
    float w = G + logf(d);
    return float_key(w);
}

// monotone-equivalent streaming key: r = d / (1e-7 - log(u+1e-7)).
// __logf guard for u>0.9996; __fdividef rel err 2^-21 covered by 0.1% band.
__device__ __forceinline__ unsigned weight_key_r(float u, float d) {
    float x = u + 1e-7f;
    float l1 = (u > 0.9996f) ? logf(x) : __logf(x);
    float inner = 1e-7f - l1;            // always > 0
    float r = __fdividef(d, inner);      // r >= 0
    return float_key(r);
}

// Block-wide "find bin containing the rem-th largest" over a shared histogram.
template <int BINS, int THREADS>
__device__ __forceinline__ void select_bin(const unsigned* h, unsigned* ss, int rem,
                                           int* out_bin, int* out_rem, unsigned* out_cnt) {
    constexpr int PER = BINS / THREADS;
    int tid = threadIdx.x;
    unsigned s = 0;
#pragma unroll
    for (int j = 0; j < PER; j++) s += h[tid * PER + j];
    ss[tid] = s;
    __syncthreads();
    for (int off = 1; off < THREADS; off <<= 1) {
        unsigned add = (tid + off < THREADS) ? ss[tid + off] : 0u;
        __syncthreads();
        ss[tid] += add;
        __syncthreads();
    }
    unsigned cumGE = ss[tid];
    unsigned cumGT = (tid < THREADS - 1) ? ss[tid + 1] : 0u;
    if (cumGE >= (unsigned)rem && cumGT < (unsigned)rem) {
        unsigned cum = cumGT;
#pragma unroll
        for (int b = PER - 1; b >= 0; --b) {
            unsigned c = h[tid * PER + b];
            if (cum + c >= (unsigned)rem) {
                *out_bin = tid * PER + b;
                *out_rem = rem - (int)cum;
                *out_cnt = c;
                break;
            }
            cum += c;
        }
    }
}

// ---------------- K0: zero hist/tickets + per-row scalars ----------------
__global__ void k_init(const float* __restrict__ t, float* __restrict__ out) {
    int gid = blockIdx.x * blockDim.x + threadIdx.x;
    int stride = gridDim.x * blockDim.x;
    for (int i = gid; i < BB * H1BINS; i += stride) g_hist1[i] = 0u;
    if (gid < BB) {
        float tv = t[gid];
        float a = 3.14159265358979323846f * tv * 0.5f;
        float r = 1.0f - cosf(a);
        int k = (int)(65536.0f * r);            // trunc like astype(int32)
        float ta = tv * 0.998f + 0.001f;
        float w = 1.5707963267948966f * sinf(3.14159265358979323846f * ta * 0.5f);
        out[(size_t)BB * NNE + gid] = w;
        g_rem[gid]   = k;
        g_p1k[gid]   = 0x10000u;     // nothing above -> all-zero mask
        g_klo[gid]   = 1u;           // empty band
        g_khi[gid]   = 0u;
        g_ccnt[gid]  = 0;
        g_tickK[gid] = 0;
        g_tickS[gid] = 0;
    }
}

// ---------------- K1: b16 r-keys + hist; LAST block per row runs selection ----------------
// grid (8, BB), 256 threads, 8192 elems/block.
__global__ void __launch_bounds__(256) k_keys(const float* __restrict__ U,
                                              const float* __restrict__ D) {
    __shared__ unsigned h[H1BINS];
    __shared__ unsigned ss[256];
    __shared__ int isLast, r_bin, r_rem;
    __shared__ unsigned r_cnt;
    int tid = threadIdx.x;
    for (int i = tid; i < H1BINS; i += 256) h[i] = 0u;
    __syncthreads();

    int row = blockIdx.y;
    int vbase = (row * NNE + blockIdx.x * 8192) >> 2;  // float4 / uint2 index
    const float4* U4 = (const float4*)U;
    const float4* D4 = (const float4*)D;
    uint2* B2 = (uint2*)g_b16;
#pragma unroll
    for (int i = 0; i < 8; i++) {
        int vi = vbase + i * 256 + tid;
        float4 u = U4[vi];
        float4 d = D4[vi];
        unsigned k0 = weight_key_r(u.x, d.x);
        unsigned k1 = weight_key_r(u.y, d.y);
        unsigned k2 = weight_key_r(u.z, d.z);
        unsigned k3 = weight_key_r(u.w, d.w);
        uint2 pk;
        pk.x = (k0 >> 16) | ((k1 >> 16) << 16);
        pk.y = (k2 >> 16) | ((k3 >> 16) << 16);
        B2[vi] = pk;
        atomicAdd(&h[k0 >> 20], 1u);
        atomicAdd(&h[k1 >> 20], 1u);
        atomicAdd(&h[k2 >> 20], 1u);
        atomicAdd(&h[k3 >> 20], 1u);
    }
    __syncthreads();
    unsigned* gh = g_hist1 + row * H1BINS;
    for (int i = tid; i < H1BINS; i += 256) {
        unsigned c = h[i];
        if (c) atomicAdd(&gh[i], c);
    }

    // ---- last-block ticket: run per-row level-1 selection in-place ----
    __threadfence();
    __syncthreads();
    if (tid == 0) isLast = (atomicAdd(&g_tickK[row], 1) == 7);
    __syncthreads();
    if (!isLast) return;
    int rem = g_rem[row];
    if (rem <= 0) return;                       // defaults select nothing
    for (int i = tid; i < H1BINS; i += 256) h[i] = __ldcg(&gh[i]);  // full hist (L2-hot)
    __syncthreads();
    select_bin<H1BINS, 256>(h, ss, rem, &r_bin, &r_rem, &r_cnt);
    __syncthreads();
    if (tid == 0) {
        unsigned p1 = (unsigned)r_bin;
        g_rem[row] = r_rem;
        g_p1k[row] = (p1 + 1u) << 4;            // b16-space threshold (bin-aligned)
        // band = selected bin extended +-0.1% multiplicative (r >= 0), then >>16
        unsigned keylo = p1 << 20;
        unsigned keyhi = ((p1 + 1u) << 20) - 1u;
        unsigned kloK = keylo, khiK = keyhi;
        float lo_f = key_to_float(keylo);
        float hi_f = key_to_float(keyhi);
        if (isfinite(lo_f)) { unsigned tt = float_key(lo_f * 0.999f); if (tt < kloK) kloK = tt; }
        if (isfinite(hi_f)) {
            float e = hi_f * 1.001f;
            unsigned tt = float_key(isfinite(e) ? e : hi_f);
            if (tt > khiK) khiK = tt;
        }
        g_klo[row] = kloK >> 16;
        g_khi[row] = khiK >> 16;
    }
}

// ---------------- K2: mask write + compaction; LAST block per row runs exact finalize ----------------
// grid (16, BB), 256 threads, 4096 elems/block.
// Shared buffer union: scan staging st = buf[0..4096);
// fin: h = buf[0..2048), ss = buf[2048..2304), tie_idx = buf[2304..6400) (cap 4096).
__global__ void __launch_bounds__(256) k_scan(float* __restrict__ out,
                                              const float* __restrict__ U,
                                              const float* __restrict__ D) {
    __shared__ unsigned buf[6400];
    __shared__ int scnt, sbase, isLast;
    __shared__ int r_bin, r_rem;
    __shared__ unsigned r_cnt;
    __shared__ int sAbove, tie_cnt;
    unsigned* st = buf;
    int tid = threadIdx.x;
    if (tid == 0) scnt = 0;
    int row = blockIdx.y;
    unsigned thr = g_p1k[row], klo = g_klo[row], khi = g_khi[row];
    __syncthreads();

    int ebase = blockIdx.x * 4096;
    int qbase = (row * NNE + ebase) >> 3;    // uint4 = 8 shorts
    const uint4* B4 = (const uint4*)g_b16;
    float4* O4 = (float4*)out;
#pragma unroll
    for (int i = 0; i < 2; i++) {
        int qi = qbase + i * 256 + tid;
        uint4 v = B4[qi];
        int e0 = ebase + ((i * 256 + tid) << 3);
        unsigned b[8];
        b[0] = v.x & 0xFFFFu; b[1] = v.x >> 16;
        b[2] = v.y & 0xFFFFu; b[3] = v.y >> 16;
        b[4] = v.z & 0xFFFFu; b[5] = v.z >> 16;
        b[6] = v.w & 0xFFFFu; b[7] = v.w >> 16;
        float4 m0, m1;
        m0.x = (b[0] >= thr) ? 1.0f : 0.0f;
        m0.y = (b[1] >= thr) ? 1.0f : 0.0f;
        m0.z = (b[2] >= thr) ? 1.0f : 0.0f;
        m0.w = (b[3] >= thr) ? 1.0f : 0.0f;
        m1.x = (b[4] >= thr) ? 1.0f : 0.0f;
        m1.y = (b[5] >= thr) ? 1.0f : 0.0f;
        m1.z = (b[6] >= thr) ? 1.0f : 0.0f;
        m1.w = (b[7] >= thr) ? 1.0f : 0.0f;
#pragma unroll
        for (int j = 0; j < 8; j++)
            if (b[j] >= klo && b[j] <= khi)
                st[atomicAdd(&scnt, 1)] = (b[j] << 16) | (unsigned)(e0 + j);
        int oi = (row * NNE + e0) >> 2;
        O4[oi]     = m0;
        O4[oi + 1] = m1;
    }
    __syncthreads();
    int c = scnt;
    if (c) {
        if (tid == 0) sbase = atomicAdd(&g_ccnt[row], c);
        __syncthreads();
        unsigned* dst = g_cand + (size_t)row * NNE + sbase;
        for (int i = tid; i < c; i += 256) dst[i] = st[i];
    }

    // ---- last-block ticket: run per-row exact finalize in-place ----
    __threadfence();
    __syncthreads();
    if (tid == 0) isLast = (atomicAdd(&g_tickS[row], 1) == 15);
    __syncthreads();
    if (!isLast) return;

    int C = __ldcg(&g_ccnt[row]);
    if (C == 0) return;
    unsigned* h = buf;            // [0..2048)
    unsigned* ss = buf + 2048;    // [2048..2304)
    unsigned* tie_idx = buf + 2304;  // cap TIE_CAP
    const unsigned* cw = g_cand + (size_t)row * NNE;
    uint2* cx = g_cand2 + (size_t)row * NNE;
    const float* Ur = U + (size_t)row * NNE;
    const float* Dr = D + (size_t)row * NNE;
    if (tid == 0) { sAbove = 0; tie_cnt = 0; }
    for (int i = tid; i < 2048; i += 256) h[i] = 0u;
    __syncthreads();

    // exact w-keys + level-1 hist (bits [31:21]) + count of provisional 1s
    int myA = 0;
    for (int i = tid; i < C; i += 256) {
        unsigned wd = __ldcg(&cw[i]);          // bypass L1 (other blocks' writes)
        unsigned idx = wd & 0xFFFFu;
        if ((wd >> 16) >= thr) myA++;
        unsigned ke = weight_key_exact(Ur[idx], Dr[idx]);
        cx[i] = make_uint2(ke, idx);
        atomicAdd(&h[ke >> 21], 1u);
    }
    if (myA) atomicAdd(&sAbove, myA);
    __syncthreads();
    int need = g_rem[row] + sAbove;
    if (need > C) need = C;
    if (need < 1) need = 1;
    select_bin<2048, 256>(h, ss, need, &r_bin, &r_rem, &r_cnt);
    __syncthreads();
    unsigned pA = (unsigned)r_bin;
    int rem = r_rem;
    __syncthreads();

    // level 2: bits [20:10]
    for (int i = tid; i < 2048; i += 256) h[i] = 0u;
    __syncthreads();
    for (int i = tid; i < C; i += 256) {
        unsigned ke = cx[i].x;
        if ((ke >> 21) == pA) atomicAdd(&h[(ke >> 10) & 2047u], 1u);
    }
    __syncthreads();
    select_bin<2048, 256>(h, ss, rem, &r_bin, &r_rem, &r_cnt);
    __syncthreads();
    unsigned pB = (unsigned)r_bin;
    rem = r_rem;
    unsigned pre22 = (pA << 11) | pB;
    __syncthreads();

    // level 3: bits [9:0]
    for (int i = tid; i < 1024; i += 256) h[i] = 0u;
    __syncthreads();
    for (int i = tid; i < C; i += 256) {
        unsigned ke = cx[i].x;
        if ((ke >> 10) == pre22) atomicAdd(&h[ke & 1023u], 1u);
    }
    __syncthreads();
    select_bin<1024, 256>(h, ss, rem, &r_bin, &r_rem, &r_cnt);
    __syncthreads();

    unsigned T = (pA << 21) | (pB << 10) | (unsigned)r_bin;
    int needT = r_rem;
    int cntT = (int)r_cnt;
    float* orow = out + (size_t)row * NNE;

    if (needT == cntT) {
        for (int i = tid; i < C; i += 256) {
            uint2 cd = cx[i];
            orow[cd.y] = (cd.x >= T) ? 1.0f : 0.0f;   // overwrite ALL candidates
        }
    } else {
        for (int i = tid; i < C; i += 256) {
            uint2 cd = cx[i];
            if (cd.x > T) orow[cd.y] = 1.0f;
            else if (cd.x < T) orow[cd.y] = 0.0f;
            else {
                int p = atomicAdd(&tie_cnt, 1);
                if (p < TIE_CAP) tie_idx[p] = cd.y;
            }
        }
        __syncthreads();
        int tc = tie_cnt < TIE_CAP ? tie_cnt : TIE_CAP;
        // stable tie-break: lowest original index first (argsort stability)
        for (int i = tid; i < tc; i += 256) {
            unsigned my = tie_idx[i];
            int rank = 0;
            for (int j = 0; j < tc; j++) rank += (tie_idx[j] < my);
            orow[my] = (rank < needT) ? 1.0f : 0.0f;
        }
    }
}

// ---------------- launch ----------------
extern "C" void kernel_launch(void* const* d_in, const int* in_sizes, int n_in,
                              void* d_out, int out_size) {
    // metadata order: batch (unused), t, U, D
    const float* t = (const float*)d_in[1];
    const float* U = (const float*)d_in[2];
    const float* D = (const float*)d_in[3];
    float* out = (float*)d_out;

    k_init<<<64, 256>>>(t, out);
    k_keys<<<dim3(8, BB), 256>>>(U, D);
    k_scan<<<dim3(16, BB), 256>>>(out, U, D);
}

// round 13
// speedup vs baseline: 1.0965x; 1.0965x over previous
#include <cuda_runtime.h>
#include <cstdint>
#include <math.h>

#define BB   256
#define NNE  65536
#define H1BINS 2048   // 11-bit level-1 on r-keys (sign + 8 exp + 2 mantissa)
#define TIE_CAP 4096

// ---------------- scratch (static device globals; no allocation) ----------------
__device__ unsigned short g_b16[(size_t)BB * NNE];   // 32 MB: top 16 bits of r-key
__device__ unsigned g_cand[(size_t)BB * NNE];        // 64 MB: (b16<<16)|idx band candidates
__device__ uint2    g_cand2[(size_t)BB * NNE];       // 128 MB: (exact wkey, idx)
__device__ unsigned g_hist1[BB * H1BINS];            // 2 MB : level-1 histograms
__device__ unsigned g_p1k[BB];    // b16 >= this  <=>  strictly above selected bin
__device__ unsigned g_klo[BB], g_khi[BB];            // inclusive b16 candidate band
__device__ int      g_rem[BB];
__device__ int      g_ccnt[BB];

// ---------------- helpers ----------------
__device__ __forceinline__ unsigned float_key(float w) {
    unsigned x = __float_as_uint(w);
    return x ^ ((unsigned)((int)x >> 31) | 0x80000000u);   // order-preserving
}
__device__ __forceinline__ float key_to_float(unsigned key) {
    unsigned x = (key & 0x80000000u) ? (key ^ 0x80000000u) : ~key;
    return __uint_as_float(x);
}

// exact key: matches the reference's float32 op-order bit-for-bit (libdevice logf)
__device__ __forceinline__ unsigned weight_key_exact(float u, float d) {
    float l1 = logf(u + 1e-7f);
    float inner = -l1 + 1e-7f;
    float G = -logf(inner);
    float w = G + logf(d);
    return float_key(w);
}

// monotone-equivalent streaming key: r = d / (1e-7 - log(u+1e-7)).
// __logf guard for u>0.9996 (abs-err amplification); __fdividef rel err 2^-21
// and FTZ effects stay within one key bin -> covered by the 0.1% band.
__device__ __forceinline__ unsigned weight_key_r(float u, float d) {
    float x = u + 1e-7f;
    float l1 = (u > 0.9996f) ? logf(x) : __logf(x);
    float inner = 1e-7f - l1;            // always > 0
    float r = __fdividef(d, inner);      // r >= 0
    return float_key(r);
}

// Block-wide "find bin containing the rem-th largest" over a shared histogram.
template <int BINS, int THREADS>
__device__ __forceinline__ void select_bin(const unsigned* h, unsigned* ss, int rem,
                                           int* out_bin, int* out_rem, unsigned* out_cnt) {
    constexpr int PER = BINS / THREADS;
    int tid = threadIdx.x;
    unsigned s = 0;
#pragma unroll
    for (int j = 0; j < PER; j++) s += h[tid * PER + j];
    ss[tid] = s;
    __syncthreads();
    for (int off = 1; off < THREADS; off <<= 1) {
        unsigned add = (tid + off < THREADS) ? ss[tid + off] : 0u;
        __syncthreads();
        ss[tid] += add;
        __syncthreads();
    }
    unsigned cumGE = ss[tid];
    unsigned cumGT = (tid < THREADS - 1) ? ss[tid + 1] : 0u;
    if (cumGE >= (unsigned)rem && cumGT < (unsigned)rem) {
        unsigned cum = cumGT;
#pragma unroll
        for (int b = PER - 1; b >= 0; --b) {
            unsigned c = h[tid * PER + b];
            if (cum + c >= (unsigned)rem) {
                *out_bin = tid * PER + b;
                *out_rem = rem - (int)cum;
                *out_cnt = c;
                break;
            }
            cum += c;
        }
    }
}

// ---------------- K0: zero hist + per-row scalars ----------------
__global__ void k_init(const float* __restrict__ t, float* __restrict__ out) {
    int gid = blockIdx.x * blockDim.x + threadIdx.x;
    int stride = gridDim.x * blockDim.x;
    for (int i = gid; i < BB * H1BINS; i += stride) g_hist1[i] = 0u;
    if (gid < BB) {
        float tv = t[gid];
        float a = 3.14159265358979323846f * tv * 0.5f;
        float r = 1.0f - cosf(a);
        int k = (int)(65536.0f * r);            // trunc like astype(int32)
        float ta = tv * 0.998f + 0.001f;
        float w = 1.5707963267948966f * sinf(3.14159265358979323846f * ta * 0.5f);
        out[(size_t)BB * NNE + gid] = w;
        g_rem[gid]  = k;
        g_p1k[gid]  = 0x10000u;      // nothing above (b16 <= 0xFFFF) -> all-zero mask
        g_klo[gid]  = 1u;            // empty band
        g_khi[gid]  = 0u;
        g_ccnt[gid] = 0;
    }
}

// ---------------- K1: b16 r-keys + 11-bit level-1 histogram (fused) ----------------
// grid (4, BB), 512 threads, 16384 elems/block -> only 4 hist flushes per row.
__global__ void __launch_bounds__(512) k_keys(const float* __restrict__ U,
                                              const float* __restrict__ D) {
    __shared__ unsigned h[H1BINS];
    int tid = threadIdx.x;
    for (int i = tid; i < H1BINS; i += 512) h[i] = 0u;
    __syncthreads();

    int row = blockIdx.y;
    int vbase = (row * NNE + blockIdx.x * 16384) >> 2;  // float4 / uint2 index
    const float4* U4 = (const float4*)U;
    const float4* D4 = (const float4*)D;
    uint2* B2 = (uint2*)g_b16;                          // uint2 = 4 b16 = 4 elements
#pragma unroll
    for (int i = 0; i < 8; i++) {
        int vi = vbase + i * 512 + tid;
        float4 u = U4[vi];
        float4 d = D4[vi];
        unsigned k0 = weight_key_r(u.x, d.x);
        unsigned k1 = weight_key_r(u.y, d.y);
        unsigned k2 = weight_key_r(u.z, d.z);
        unsigned k3 = weight_key_r(u.w, d.w);
        uint2 pk;
        pk.x = (k0 >> 16) | ((k1 >> 16) << 16);
        pk.y = (k2 >> 16) | ((k3 >> 16) << 16);
        B2[vi] = pk;
        atomicAdd(&h[k0 >> 21], 1u);
        atomicAdd(&h[k1 >> 21], 1u);
        atomicAdd(&h[k2 >> 21], 1u);
        atomicAdd(&h[k3 >> 21], 1u);
    }
    __syncthreads();
    unsigned* gh = g_hist1 + row * H1BINS;
    for (int i = tid; i < H1BINS; i += 512) {
        unsigned c = h[i];
        if (c) atomicAdd(&gh[i], c);
    }
}

// ---------------- K2: level-1 bin selection + band bounds (one block / row) ----------------
__global__ void __launch_bounds__(256) k_sel1() {
    int row = blockIdx.x;
    if (g_rem[row] <= 0) return;                 // defaults select nothing
    int tid = threadIdx.x;
    __shared__ unsigned sh[H1BINS];
    __shared__ unsigned ss[256];
    __shared__ int r_bin, r_rem;
    __shared__ unsigned r_cnt;
    for (int i = tid; i < H1BINS; i += 256) sh[i] = g_hist1[row * H1BINS + i];
    int rem = g_rem[row];
    __syncthreads();
    select_bin<H1BINS, 256>(sh, ss, rem, &r_bin, &r_rem, &r_cnt);
    __syncthreads();
    if (tid == 0) {
        unsigned p1 = (unsigned)r_bin;
        g_rem[row] = r_rem;
        g_p1k[row] = (p1 + 1u) << 5;                  // b16-space threshold (bin-aligned)
        // band = selected bin extended +-0.1% multiplicative (r >= 0), then >>16
        unsigned keylo = p1 << 21;
        unsigned keyhi = ((p1 + 1u) << 21) - 1u;      // wraps to 0xFFFFFFFF for p1=2047
        unsigned kloK = keylo, khiK = keyhi;
        float lo_f = key_to_float(keylo);
        float hi_f = key_to_float(keyhi);
        if (isfinite(lo_f)) { unsigned tt = float_key(lo_f * 0.999f); if (tt < kloK) kloK = tt; }
        if (isfinite(hi_f)) {
            float e = hi_f * 1.001f;
            unsigned tt = float_key(isfinite(e) ? e : hi_f);
            if (tt > khiK) khiK = tt;
        }
        g_klo[row] = kloK >> 16;
        g_khi[row] = khiK >> 16;
    }
}

// ---------------- K3: mask write + band-candidate compaction ----------------
// grid (16, BB), 256 threads, 4096 elems/block; 8 elems/thread/iter via uint4.
__global__ void __launch_bounds__(256) k_scan(float* __restrict__ out) {
    __shared__ unsigned st[4096];
    __shared__ int scnt, sbase;
    int tid = threadIdx.x;
    if (tid == 0) scnt = 0;
    int row = blockIdx.y;
    unsigned thr = g_p1k[row], klo = g_klo[row], khi = g_khi[row];
    __syncthreads();

    int ebase = blockIdx.x * 4096;
    int qbase = (row * NNE + ebase) >> 3;    // uint4 = 8 shorts
    const uint4* B4 = (const uint4*)g_b16;
    float4* O4 = (float4*)out;
#pragma unroll
    for (int i = 0; i < 2; i++) {
        int qi = qbase + i * 256 + tid;
        uint4 v = B4[qi];
        int e0 = ebase + ((i * 256 + tid) << 3);
        unsigned b[8];
        b[0] = v.x & 0xFFFFu; b[1] = v.x >> 16;
        b[2] = v.y & 0xFFFFu; b[3] = v.y >> 16;
        b[4] = v.z & 0xFFFFu; b[5] = v.z >> 16;
        b[6] = v.w & 0xFFFFu; b[7] = v.w >> 16;
        float4 m0, m1;
        m0.x = (b[0] >= thr) ? 1.0f : 0.0f;
        m0.y = (b[1] >= thr) ? 1.0f : 0.0f;
        m0.z = (b[2] >= thr) ? 1.0f : 0.0f;
        m0.w = (b[3] >= thr) ? 1.0f : 0.0f;
        m1.x = (b[4] >= thr) ? 1.0f : 0.0f;
        m1.y = (b[5] >= thr) ? 1.0f : 0.0f;
        m1.z = (b[6] >= thr) ? 1.0f : 0.0f;
        m1.w = (b[7] >= thr) ? 1.0f : 0.0f;
#pragma unroll
        for (int j = 0; j < 8; j++)
            if (b[j] >= klo && b[j] <= khi)
                st[atomicAdd(&scnt, 1)] = (b[j] << 16) | (unsigned)(e0 + j);
        int oi = (row * NNE + e0) >> 2;
        O4[oi]     = m0;
        O4[oi + 1] = m1;
    }
    __syncthreads();
    int c = scnt;
    if (c) {
        if (tid == 0) sbase = atomicAdd(&g_ccnt[row], c);
        __syncthreads();
        unsigned* dst = g_cand + (size_t)row * NNE + sbase;
        for (int i = tid; i < c; i += 256) dst[i] = st[i];
    }
}

// ---------------- K4: exact recompute on candidates + 3-level drill + final mask ----------------
__global__ void __launch_bounds__(1024) k_fin(float* __restrict__ out,
                                              const float* __restrict__ U,
                                              const float* __restrict__ D) {
    int row = blockIdx.x;
    int C = g_ccnt[row];
    if (C == 0) return;
    int tid = threadIdx.x;
    __shared__ unsigned h[2048];
    __shared__ unsigned ss[1024];
    __shared__ int r_bin, r_rem;
    __shared__ unsigned r_cnt;
    __shared__ int sAbove, tie_cnt;
    __shared__ unsigned tie_idx[TIE_CAP];

    unsigned thr = g_p1k[row];
    const unsigned* cw = g_cand + (size_t)row * NNE;
    uint2* cx = g_cand2 + (size_t)row * NNE;
    const float* Ur = U + (size_t)row * NNE;
    const float* Dr = D + (size_t)row * NNE;
    if (tid == 0) { sAbove = 0; tie_cnt = 0; }
    h[tid] = 0u; h[tid + 1024] = 0u;
    __syncthreads();

    // exact w-keys + level-1 hist (bits [31:21]) + count of provisional 1s among candidates
    int myA = 0;
    for (int i = tid; i < C; i += 1024) {
        unsigned wd = cw[i];
        unsigned idx = wd & 0xFFFFu;
        if ((wd >> 16) >= thr) myA++;
        unsigned ke = weight_key_exact(Ur[idx], Dr[idx]);
        cx[i] = make_uint2(ke, idx);
        atomicAdd(&h[ke >> 21], 1u);
    }
    if (myA) atomicAdd(&sAbove, myA);
    __syncthreads();
    int need = g_rem[row] + sAbove;    // k-th overall == need-th within candidates
    if (need > C) need = C;
    if (need < 1) need = 1;
    select_bin<2048, 1024>(h, ss, need, &r_bin, &r_rem, &r_cnt);
    __syncthreads();
    unsigned pA = (unsigned)r_bin;
    int rem = r_rem;
    __syncthreads();

    // level 2: bits [20:10]
    h[tid] = 0u; h[tid + 1024] = 0u;
    __syncthreads();
    for (int i = tid; i < C; i += 1024) {
        unsigned ke = cx[i].x;
        if ((ke >> 21) == pA) atomicAdd(&h[(ke >> 10) & 2047u], 1u);
    }
    __syncthreads();
    select_bin<2048, 1024>(h, ss, rem, &r_bin, &r_rem, &r_cnt);
    __syncthreads();
    unsigned pB = (unsigned)r_bin;
    rem = r_rem;
    unsigned pre22 = (pA << 11) | pB;
    __syncthreads();

    // level 3: bits [9:0]
    h[tid] = 0u;
    __syncthreads();
    for (int i = tid; i < C; i += 1024) {
        unsigned ke = cx[i].x;
        if ((ke >> 10) == pre22) atomicAdd(&h[ke & 1023u], 1u);
    }
    __syncthreads();
    select_bin<1024, 1024>(h, ss, rem, &r_bin, &r_rem, &r_cnt);
    __syncthreads();

    unsigned T = (pA << 21) | (pB << 10) | (unsigned)r_bin;
    int needT = r_rem;
    int cntT = (int)r_cnt;
    float* orow = out + (size_t)row * NNE;

    if (needT == cntT) {
        for (int i = tid; i < C; i += 1024) {
            uint2 cd = cx[i];
            orow[cd.y] = (cd.x >= T) ? 1.0f : 0.0f;   // overwrite ALL candidates
        }
    } else {
        for (int i = tid; i < C; i += 1024) {
            uint2 cd = cx[i];
            if (cd.x > T) orow[cd.y] = 1.0f;
            else if (cd.x < T) orow[cd.y] = 0.0f;
            else {
                int p = atomicAdd(&tie_cnt, 1);
                if (p < TIE_CAP) tie_idx[p] = cd.y;
            }
        }
        __syncthreads();
        int tc = tie_cnt < TIE_CAP ? tie_cnt : TIE_CAP;
        // stable tie-break: lowest original index first (argsort stability)
        for (int i = tid; i < tc; i += 1024) {
            unsigned my = tie_idx[i];
            int rank = 0;
            for (int j = 0; j < tc; j++) rank += (tie_idx[j] < my);
            orow[my] = (rank < needT) ? 1.0f : 0.0f;
        }
    }
}

// ---------------- launch ----------------
extern "C" void kernel_launch(void* const* d_in, const int* in_sizes, int n_in,
                              void* d_out, int out_size) {
    // metadata order: batch (unused), t, U, D
    const float* t = (const float*)d_in[1];
    const float* U = (const float*)d_in[2];
    const float* D = (const float*)d_in[3];
    float* out = (float*)d_out;

    k_init<<<256, 256>>>(t, out);
    k_keys<<<dim3(4, BB), 512>>>(U, D);
    k_sel1<<<BB, 256>>>();
    k_scan<<<dim3(16, BB), 256>>>(out);
    k_fin<<<BB, 1024>>>(out, U, D);
}

// round 14
// speedup vs baseline: 1.1417x; 1.0412x over previous
#include <cuda_runtime.h>
#include <cstdint>
#include <math.h>

#define BB   256
#define NNE  65536
#define H1BINS 4096   // 12-bit level-1 on r-keys (sign + 8 exp + 3 mantissa)
#define KB_PER_ROW 4  // partial hists per row
#define TIE_CAP 4096

// ---------------- scratch (static device globals; no allocation) ----------------
__device__ unsigned short g_b16[(size_t)BB * NNE];   // 32 MB: top 16 bits of r-key
__device__ unsigned g_cand[(size_t)BB * NNE];        // 64 MB: (b16<<16)|idx band candidates
__device__ uint2    g_cand2[(size_t)BB * NNE];       // 128 MB: (exact wkey, idx)
__device__ unsigned g_hist1[(size_t)BB * KB_PER_ROW * H1BINS];  // 16 MB: private partial hists
__device__ unsigned g_p1k[BB];    // b16 >= this  <=>  strictly above selected bin
__device__ unsigned g_klo[BB], g_khi[BB];            // inclusive b16 candidate band
__device__ int      g_rem[BB];
__device__ int      g_ccnt[BB];

// ---------------- helpers ----------------
__device__ __forceinline__ unsigned float_key(float w) {
    unsigned x = __float_as_uint(w);
    return x ^ ((unsigned)((int)x >> 31) | 0x80000000u);   // order-preserving
}
__device__ __forceinline__ float key_to_float(unsigned key) {
    unsigned x = (key & 0x80000000u) ? (key ^ 0x80000000u) : ~key;
    return __uint_as_float(x);
}

// exact key: matches the reference's float32 op-order bit-for-bit (libdevice logf)
__device__ __forceinline__ unsigned weight_key_exact(float u, float d) {
    float l1 = logf(u + 1e-7f);
    float inner = -l1 + 1e-7f;
    float G = -logf(inner);
    float w = G + logf(d);
    return float_key(w);
}

// monotone-equivalent streaming key: r = d / (1e-7 - log(u+1e-7)).
// __logf guard for u>0.9996 (abs-err amplification); __fdividef rel err 2^-21
// and FTZ effects stay within one key bin -> covered by the 0.1% band.
__device__ __forceinline__ unsigned weight_key_r(float u, float d) {
    float x = u + 1e-7f;
    float l1 = (u > 0.9996f) ? logf(x) : __logf(x);
    float inner = 1e-7f - l1;            // always > 0
    float r = __fdividef(d, inner);      // r >= 0
    return float_key(r);
}

// Block-wide "find bin containing the rem-th largest" over a shared histogram.
template <int BINS, int THREADS>
__device__ __forceinline__ void select_bin(const unsigned* h, unsigned* ss, int rem,
                                           int* out_bin, int* out_rem, unsigned* out_cnt) {
    constexpr int PER = BINS / THREADS;
    int tid = threadIdx.x;
    unsigned s = 0;
#pragma unroll
    for (int j = 0; j < PER; j++) s += h[tid * PER + j];
    ss[tid] = s;
    __syncthreads();
    for (int off = 1; off < THREADS; off <<= 1) {
        unsigned add = (tid + off < THREADS) ? ss[tid + off] : 0u;
        __syncthreads();
        ss[tid] += add;
        __syncthreads();
    }
    unsigned cumGE = ss[tid];
    unsigned cumGT = (tid < THREADS - 1) ? ss[tid + 1] : 0u;
    if (cumGE >= (unsigned)rem && cumGT < (unsigned)rem) {
        unsigned cum = cumGT;
#pragma unroll
        for (int b = PER - 1; b >= 0; --b) {
            unsigned c = h[tid * PER + b];
            if (cum + c >= (unsigned)rem) {
                *out_bin = tid * PER + b;
                *out_rem = rem - (int)cum;
                *out_cnt = c;
                break;
            }
            cum += c;
        }
    }
}

// ---------------- K1: b16 r-keys + PRIVATE 12-bit histogram (plain stores) ----------------
// grid (4, BB), 512 threads, 16384 elems/block. No init dependency, no RED.
__global__ void __launch_bounds__(512) k_keys(const float* __restrict__ U,
                                              const float* __restrict__ D) {
    __shared__ unsigned h[H1BINS];
    int tid = threadIdx.x;
    for (int i = tid; i < H1BINS; i += 512) h[i] = 0u;
    __syncthreads();

    int row = blockIdx.y;
    int vbase = (row * NNE + blockIdx.x * 16384) >> 2;  // float4 / uint2 index
    const float4* U4 = (const float4*)U;
    const float4* D4 = (const float4*)D;
    uint2* B2 = (uint2*)g_b16;                          // uint2 = 4 b16 = 4 elements
#pragma unroll
    for (int i = 0; i < 8; i++) {
        int vi = vbase + i * 512 + tid;
        float4 u = U4[vi];
        float4 d = D4[vi];
        unsigned k0 = weight_key_r(u.x, d.x);
        unsigned k1 = weight_key_r(u.y, d.y);
        unsigned k2 = weight_key_r(u.z, d.z);
        unsigned k3 = weight_key_r(u.w, d.w);
        uint2 pk;
        pk.x = (k0 >> 16) | ((k1 >> 16) << 16);
        pk.y = (k2 >> 16) | ((k3 >> 16) << 16);
        B2[vi] = pk;
        atomicAdd(&h[k0 >> 20], 1u);
        atomicAdd(&h[k1 >> 20], 1u);
        atomicAdd(&h[k2 >> 20], 1u);
        atomicAdd(&h[k3 >> 20], 1u);
    }
    __syncthreads();
    // private slice: plain coalesced stores, no atomics
    unsigned* gh = g_hist1 + ((size_t)row * KB_PER_ROW + blockIdx.x) * H1BINS;
    for (int i = tid; i < H1BINS; i += 512) gh[i] = h[i];
}

// ---------------- K2: per-row scalars + level-1 selection + band (one block / row) ----------------
__global__ void __launch_bounds__(256) k_sel1(const float* __restrict__ t,
                                              float* __restrict__ out) {
    int row = blockIdx.x;
    int tid = threadIdx.x;
    __shared__ unsigned sh[H1BINS];
    __shared__ unsigned ss[256];
    __shared__ int s_k;
    __shared__ int r_bin, r_rem;
    __shared__ unsigned r_cnt;

    if (tid == 0) {
        float tv = t[row];
        float a = 3.14159265358979323846f * tv * 0.5f;
        float rr = 1.0f - cosf(a);
        int k = (int)(65536.0f * rr);           // trunc like astype(int32)
        float ta = tv * 0.998f + 0.001f;
        float w = 1.5707963267948966f * sinf(3.14159265358979323846f * ta * 0.5f);
        out[(size_t)BB * NNE + row] = w;
        g_ccnt[row] = 0;
        s_k = k;
    }
    __syncthreads();
    int kk = s_k;
    if (kk <= 0) {
        if (tid == 0) {
            g_rem[row] = 0;
            g_p1k[row] = 0x10000u;   // nothing above -> all-zero mask
            g_klo[row] = 1u;         // empty band
            g_khi[row] = 0u;
        }
        return;
    }
    // sum the 4 private hist slices
    const unsigned* h0 = g_hist1 + (size_t)row * KB_PER_ROW * H1BINS;
    for (int i = tid; i < H1BINS; i += 256)
        sh[i] = h0[i] + h0[H1BINS + i] + h0[2 * H1BINS + i] + h0[3 * H1BINS + i];
    __syncthreads();
    select_bin<H1BINS, 256>(sh, ss, kk, &r_bin, &r_rem, &r_cnt);
    __syncthreads();
    if (tid == 0) {
        unsigned p1 = (unsigned)r_bin;
        g_rem[row] = r_rem;
        g_p1k[row] = (p1 + 1u) << 4;                  // b16-space threshold (bin-aligned)
        // band = selected bin extended +-0.1% multiplicative (r >= 0), then >>16
        unsigned keylo = p1 << 20;
        unsigned keyhi = ((p1 + 1u) << 20) - 1u;      // 0xFFFFFFFF for p1=4095
        unsigned kloK = keylo, khiK = keyhi;
        float lo_f = key_to_float(keylo);
        float hi_f = key_to_float(keyhi);
        if (isfinite(lo_f)) { unsigned tt = float_key(lo_f * 0.999f); if (tt < kloK) kloK = tt; }
        if (isfinite(hi_f)) {
            float e = hi_f * 1.001f;
            unsigned tt = float_key(isfinite(e) ? e : hi_f);
            if (tt > khiK) khiK = tt;
        }
        g_klo[row] = kloK >> 16;
        g_khi[row] = khiK >> 16;
    }
}

// ---------------- K3: mask write + band-candidate compaction (proven shape) ----------------
// grid (16, BB), 256 threads, 4096 elems/block; 8 elems/thread/iter via uint4.
__global__ void __launch_bounds__(256) k_scan(float* __restrict__ out) {
    __shared__ unsigned st[4096];
    __shared__ int scnt, sbase;
    int tid = threadIdx.x;
    if (tid == 0) scnt = 0;
    int row = blockIdx.y;
    unsigned thr = g_p1k[row], klo = g_klo[row], khi = g_khi[row];
    __syncthreads();

    int ebase = blockIdx.x * 4096;
    int qbase = (row * NNE + ebase) >> 3;    // uint4 = 8 shorts
    const uint4* B4 = (const uint4*)g_b16;
    float4* O4 = (float4*)out;
#pragma unroll
    for (int i = 0; i < 2; i++) {
        int qi = qbase + i * 256 + tid;
        uint4 v = B4[qi];
        int e0 = ebase + ((i * 256 + tid) << 3);
        unsigned b[8];
        b[0] = v.x & 0xFFFFu; b[1] = v.x >> 16;
        b[2] = v.y & 0xFFFFu; b[3] = v.y >> 16;
        b[4] = v.z & 0xFFFFu; b[5] = v.z >> 16;
        b[6] = v.w & 0xFFFFu; b[7] = v.w >> 16;
        float4 m0, m1;
        m0.x = (b[0] >= thr) ? 1.0f : 0.0f;
        m0.y = (b[1] >= thr) ? 1.0f : 0.0f;
        m0.z = (b[2] >= thr) ? 1.0f : 0.0f;
        m0.w = (b[3] >= thr) ? 1.0f : 0.0f;
        m1.x = (b[4] >= thr) ? 1.0f : 0.0f;
        m1.y = (b[5] >= thr) ? 1.0f : 0.0f;
        m1.z = (b[6] >= thr) ? 1.0f : 0.0f;
        m1.w = (b[7] >= thr) ? 1.0f : 0.0f;
#pragma unroll
        for (int j = 0; j < 8; j++)
            if (b[j] >= klo && b[j] <= khi)
                st[atomicAdd(&scnt, 1)] = (b[j] << 16) | (unsigned)(e0 + j);
        int oi = (row * NNE + e0) >> 2;
        O4[oi]     = m0;
        O4[oi + 1] = m1;
    }
    __syncthreads();
    int c = scnt;
    if (c) {
        if (tid == 0) sbase = atomicAdd(&g_ccnt[row], c);
        __syncthreads();
        unsigned* dst = g_cand + (size_t)row * NNE + sbase;
        for (int i = tid; i < c; i += 256) dst[i] = st[i];
    }
}

// ---------------- K4: exact recompute on candidates + 3-level drill + final mask ----------------
__global__ void __launch_bounds__(1024) k_fin(float* __restrict__ out,
                                              const float* __restrict__ U,
                                              const float* __restrict__ D) {
    int row = blockIdx.x;
    int C = g_ccnt[row];
    if (C == 0) return;
    int tid = threadIdx.x;
    __shared__ unsigned h[2048];
    __shared__ unsigned ss[1024];
    __shared__ int r_bin, r_rem;
    __shared__ unsigned r_cnt;
    __shared__ int sAbove, tie_cnt;
    __shared__ unsigned tie_idx[TIE_CAP];

    unsigned thr = g_p1k[row];
    const unsigned* cw = g_cand + (size_t)row * NNE;
    uint2* cx = g_cand2 + (size_t)row * NNE;
    const float* Ur = U + (size_t)row * NNE;
    const float* Dr = D + (size_t)row * NNE;
    if (tid == 0) { sAbove = 0; tie_cnt = 0; }
    h[tid] = 0u; h[tid + 1024] = 0u;
    __syncthreads();

    // exact w-keys + level-1 hist (bits [31:21]) + count of provisional 1s
    int myA = 0;
    for (int i = tid; i < C; i += 1024) {
        unsigned wd = cw[i];
        unsigned idx = wd & 0xFFFFu;
        if ((wd >> 16) >= thr) myA++;
        unsigned ke = weight_key_exact(Ur[idx], Dr[idx]);
        cx[i] = make_uint2(ke, idx);
        atomicAdd(&h[ke >> 21], 1u);
    }
    if (myA) atomicAdd(&sAbove, myA);
    __syncthreads();
    int need = g_rem[row] + sAbove;    // k-th overall == need-th within candidates
    if (need > C) need = C;
    if (need < 1) need = 1;
    select_bin<2048, 1024>(h, ss, need, &r_bin, &r_rem, &r_cnt);
    __syncthreads();
    unsigned pA = (unsigned)r_bin;
    int rem = r_rem;
    __syncthreads();

    // level 2: bits [20:10]
    h[tid] = 0u; h[tid + 1024] = 0u;
    __syncthreads();
    for (int i = tid; i < C; i += 1024) {
        unsigned ke = cx[i].x;
        if ((ke >> 21) == pA) atomicAdd(&h[(ke >> 10) & 2047u], 1u);
    }
    __syncthreads();
    select_bin<2048, 1024>(h, ss, rem, &r_bin, &r_rem, &r_cnt);
    __syncthreads();
    unsigned pB = (unsigned)r_bin;
    rem = r_rem;
    unsigned pre22 = (pA << 11) | pB;
    __syncthreads();

    // level 3: bits [9:0]
    h[tid] = 0u;
    __syncthreads();
    for (int i = tid; i < C; i += 1024) {
        unsigned ke = cx[i].x;
        if ((ke >> 10) == pre22) atomicAdd(&h[ke & 1023u], 1u);
    }
    __syncthreads();
    select_bin<1024, 1024>(h, ss, rem, &r_bin, &r_rem, &r_cnt);
    __syncthreads();

    unsigned T = (pA << 21) | (pB << 10) | (unsigned)r_bin;
    int needT = r_rem;
    int cntT = (int)r_cnt;
    float* orow = out + (size_t)row * NNE;

    if (needT == cntT) {
        for (int i = tid; i < C; i += 1024) {
            uint2 cd = cx[i];
            orow[cd.y] = (cd.x >= T) ? 1.0f : 0.0f;   // overwrite ALL candidates
        }
    } else {
        for (int i = tid; i < C; i += 1024) {
            uint2 cd = cx[i];
            if (cd.x > T) orow[cd.y] = 1.0f;
            else if (cd.x < T) orow[cd.y] = 0.0f;
            else {
                int p = atomicAdd(&tie_cnt, 1);
                if (p < TIE_CAP) tie_idx[p] = cd.y;
            }
        }
        __syncthreads();
        int tc = tie_cnt < TIE_CAP ? tie_cnt : TIE_CAP;
        // stable tie-break: lowest original index first (argsort stability)
        for (int i = tid; i < tc; i += 1024) {
            unsigned my = tie_idx[i];
            int rank = 0;
            for (int j = 0; j < tc; j++) rank += (tie_idx[j] < my);
            orow[my] = (rank < needT) ? 1.0f : 0.0f;
        }
    }
}

// ---------------- launch ----------------
extern "C" void kernel_launch(void* const* d_in, const int* in_sizes, int n_in,
                              void* d_out, int out_size) {
    // metadata order: batch (unused), t, U, D
    const float* t = (const float*)d_in[1];
    const float* U = (const float*)d_in[2];
    const float* D = (const float*)d_in[3];
    float* out = (float*)d_out;

    k_keys<<<dim3(KB_PER_ROW, BB), 512>>>(U, D);
    k_sel1<<<BB, 256>>>(t, out);
    k_scan<<<dim3(16, BB), 256>>>(out);
    k_fin<<<BB, 1024>>>(out, U, D);
}

// round 16
// speedup vs baseline: 1.2581x; 1.1020x over previous
#include <cuda_runtime.h>
#include <cstdint>
#include <math.h>

#define BB   256
#define NNE  65536
#define H1BINS 2048   // 11-bit level-1 on r-keys (sign + 8 exp + 2 mantissa)
#define KB_PER_ROW 4  // partial hists per row
#define TIE_CAP 4096

// ---------------- scratch (static device globals; no allocation) ----------------
__device__ unsigned short g_b16[(size_t)BB * NNE];   // 32 MB: top 16 bits of r-key
__device__ unsigned g_cand[(size_t)BB * NNE];        // 64 MB: (b16<<16)|idx band candidates
__device__ uint2    g_cand2[(size_t)BB * NNE];       // 128 MB: (exact wkey, idx) mid set
__device__ unsigned g_hist1[(size_t)BB * KB_PER_ROW * H1BINS];  // 8 MB: private partial hists
__device__ unsigned g_p1k[BB];    // b16 >= this  <=>  strictly above selected bin
__device__ unsigned g_klo[BB], g_khi[BB];            // inclusive b16 candidate band
__device__ int      g_rem[BB];
__device__ int      g_ccnt[BB];

// ---------------- helpers ----------------
__device__ __forceinline__ unsigned float_key(float w) {
    unsigned x = __float_as_uint(w);
    return x ^ ((unsigned)((int)x >> 31) | 0x80000000u);   // order-preserving
}
__device__ __forceinline__ float key_to_float(unsigned key) {
    unsigned x = (key & 0x80000000u) ? (key ^ 0x80000000u) : ~key;
    return __uint_as_float(x);
}

// exact key: matches the reference's float32 op-order bit-for-bit (libdevice logf)
__device__ __forceinline__ unsigned weight_key_exact(float u, float d) {
    float l1 = logf(u + 1e-7f);
    float inner = -l1 + 1e-7f;
    float G = -logf(inner);
    float w = G + logf(d);
    return float_key(w);
}

// monotone-equivalent streaming key: r = d / (1e-7 - log(u+1e-7)).
// __logf guard for u>0.9996; __fdividef rel err 2^-21; all approx errors
// << one b16 quantum (2^-7 rel) -> covered by the 0.1% band + the +-1-quantum
// mid window in k_fin.
__device__ __forceinline__ unsigned weight_key_r(float u, float d) {
    float x = u + 1e-7f;
    float l1 = (u > 0.9996f) ? logf(x) : __logf(x);
    float inner = 1e-7f - l1;            // always > 0
    float r = __fdividef(d, inner);      // r >= 0
    return float_key(r);
}

// Block-wide "find bin containing the rem-th largest" over a shared histogram.
template <int BINS, int THREADS>
__device__ __forceinline__ void select_bin(const unsigned* h, unsigned* ss, int rem,
                                           int* out_bin, int* out_rem, unsigned* out_cnt) {
    constexpr int PER = BINS / THREADS;
    int tid = threadIdx.x;
    unsigned s = 0;
#pragma unroll
    for (int j = 0; j < PER; j++) s += h[tid * PER + j];
    ss[tid] = s;
    __syncthreads();
    for (int off = 1; off < THREADS; off <<= 1) {
        unsigned add = (tid + off < THREADS) ? ss[tid + off] : 0u;
        __syncthreads();
        ss[tid] += add;
        __syncthreads();
    }
    unsigned cumGE = ss[tid];
    unsigned cumGT = (tid < THREADS - 1) ? ss[tid + 1] : 0u;
    if (cumGE >= (unsigned)rem && cumGT < (unsigned)rem) {
        unsigned cum = cumGT;
#pragma unroll
        for (int b = PER - 1; b >= 0; --b) {
            unsigned c = h[tid * PER + b];
            if (cum + c >= (unsigned)rem) {
                *out_bin = tid * PER + b;
                *out_rem = rem - (int)cum;
                *out_cnt = c;
                break;
            }
            cum += c;
        }
    }
}

// ---------------- K1: b16 r-keys + PRIVATE 11-bit histogram (plain stores) ----------------
// grid (4, BB), 512 threads, 16384 elems/block. No init dependency, no RED.
__global__ void __launch_bounds__(512) k_keys(const float* __restrict__ U,
                                              const float* __restrict__ D) {
    __shared__ unsigned h[H1BINS];
    int tid = threadIdx.x;
    for (int i = tid; i < H1BINS; i += 512) h[i] = 0u;
    __syncthreads();

    int row = blockIdx.y;
    int vbase = (row * NNE + blockIdx.x * 16384) >> 2;  // float4 / uint2 index
    const float4* U4 = (const float4*)U;
    const float4* D4 = (const float4*)D;
    uint2* B2 = (uint2*)g_b16;                          // uint2 = 4 b16 = 4 elements
#pragma unroll
    for (int i = 0; i < 8; i++) {
        int vi = vbase + i * 512 + tid;
        float4 u = U4[vi];
        float4 d = D4[vi];
        unsigned k0 = weight_key_r(u.x, d.x);
        unsigned k1 = weight_key_r(u.y, d.y);
        unsigned k2 = weight_key_r(u.z, d.z);
        unsigned k3 = weight_key_r(u.w, d.w);
        uint2 pk;
        pk.x = (k0 >> 16) | ((k1 >> 16) << 16);
        pk.y = (k2 >> 16) | ((k3 >> 16) << 16);
        B2[vi] = pk;
        atomicAdd(&h[k0 >> 21], 1u);
        atomicAdd(&h[k1 >> 21], 1u);
        atomicAdd(&h[k2 >> 21], 1u);
        atomicAdd(&h[k3 >> 21], 1u);
    }
    __syncthreads();
    // private slice: plain coalesced stores, no atomics
    unsigned* gh = g_hist1 + ((size_t)row * KB_PER_ROW + blockIdx.x) * H1BINS;
    for (int i = tid; i < H1BINS; i += 512) gh[i] = h[i];
}

// ---------------- K2: per-row scalars + level-1 selection + band (one block / row) ----------------
__global__ void __launch_bounds__(256) k_sel1(const float* __restrict__ t,
                                              float* __restrict__ out) {
    int row = blockIdx.x;
    int tid = threadIdx.x;
    __shared__ unsigned sh[H1BINS];
    __shared__ unsigned ss[256];
    __shared__ int s_k;
    __shared__ int r_bin, r_rem;
    __shared__ unsigned r_cnt;

    if (tid == 0) {
        float tv = t[row];
        float a = 3.14159265358979323846f * tv * 0.5f;
        float rr = 1.0f - cosf(a);
        int k = (int)(65536.0f * rr);           // trunc like astype(int32)
        float ta = tv * 0.998f + 0.001f;
        float w = 1.5707963267948966f * sinf(3.14159265358979323846f * ta * 0.5f);
        out[(size_t)BB * NNE + row] = w;
        g_ccnt[row] = 0;
        s_k = k;
    }
    __syncthreads();
    int kk = s_k;
    if (kk <= 0) {
        if (tid == 0) {
            g_rem[row] = 0;
            g_p1k[row] = 0x10000u;   // nothing above -> all-zero mask
            g_klo[row] = 1u;         // empty band
            g_khi[row] = 0u;
        }
        return;
    }
    // sum the 4 private hist slices
    const unsigned* h0 = g_hist1 + (size_t)row * KB_PER_ROW * H1BINS;
    for (int i = tid; i < H1BINS; i += 256)
        sh[i] = h0[i] + h0[H1BINS + i] + h0[2 * H1BINS + i] + h0[3 * H1BINS + i];
    __syncthreads();
    select_bin<H1BINS, 256>(sh, ss, kk, &r_bin, &r_rem, &r_cnt);
    __syncthreads();
    if (tid == 0) {
        unsigned p1 = (unsigned)r_bin;
        g_rem[row] = r_rem;
        g_p1k[row] = (p1 + 1u) << 5;                  // b16-space threshold (bin-aligned)
        // band = selected bin extended +-0.1% multiplicative (r >= 0), then >>16
        unsigned keylo = p1 << 21;
        unsigned keyhi = ((p1 + 1u) << 21) - 1u;      // 0xFFFFFFFF for p1=2047
        unsigned kloK = keylo, khiK = keyhi;
        float lo_f = key_to_float(keylo);
        float hi_f = key_to_float(keyhi);
        if (isfinite(lo_f)) { unsigned tt = float_key(lo_f * 0.999f); if (tt < kloK) kloK = tt; }
        if (isfinite(hi_f)) {
            float e = hi_f * 1.001f;
            unsigned tt = float_key(isfinite(e) ? e : hi_f);
            if (tt > khiK) khiK = tt;
        }
        g_klo[row] = kloK >> 16;
        g_khi[row] = khiK >> 16;
    }
}

// ---------------- K3: mask write + band-candidate compaction (proven shape) ----------------
// grid (16, BB), 256 threads, 4096 elems/block; 8 elems/thread/iter via uint4.
__global__ void __launch_bounds__(256) k_scan(float* __restrict__ out) {
    __shared__ unsigned st[4096];
    __shared__ int scnt, sbase;
    int tid = threadIdx.x;
    if (tid == 0) scnt = 0;
    int row = blockIdx.y;
    unsigned thr = g_p1k[row], klo = g_klo[row], khi = g_khi[row];
    __syncthreads();

    int ebase = blockIdx.x * 4096;
    int qbase = (row * NNE + ebase) >> 3;    // uint4 = 8 shorts
    const uint4* B4 = (const uint4*)g_b16;
    float4* O4 = (float4*)out;
#pragma unroll
    for (int i = 0; i < 2; i++) {
        int qi = qbase + i * 256 + tid;
        uint4 v = B4[qi];
        int e0 = ebase + ((i * 256 + tid) << 3);
        unsigned b[8];
        b[0] = v.x & 0xFFFFu; b[1] = v.x >> 16;
        b[2] = v.y & 0xFFFFu; b[3] = v.y >> 16;
        b[4] = v.z & 0xFFFFu; b[5] = v.z >> 16;
        b[6] = v.w & 0xFFFFu; b[7] = v.w >> 16;
        float4 m0, m1;
        m0.x = (b[0] >= thr) ? 1.0f : 0.0f;
        m0.y = (b[1] >= thr) ? 1.0f : 0.0f;
        m0.z = (b[2] >= thr) ? 1.0f : 0.0f;
        m0.w = (b[3] >= thr) ? 1.0f : 0.0f;
        m1.x = (b[4] >= thr) ? 1.0f : 0.0f;
        m1.y = (b[5] >= thr) ? 1.0f : 0.0f;
        m1.z = (b[6] >= thr) ? 1.0f : 0.0f;
        m1.w = (b[7] >= thr) ? 1.0f : 0.0f;
#pragma unroll
        for (int j = 0; j < 8; j++)
            if (b[j] >= klo && b[j] <= khi)
                st[atomicAdd(&scnt, 1)] = (b[j] << 16) | (unsigned)(e0 + j);
        int oi = (row * NNE + e0) >> 2;
        O4[oi]     = m0;
        O4[oi + 1] = m1;
    }
    __syncthreads();
    int c = scnt;
    if (c) {
        if (tid == 0) sbase = atomicAdd(&g_ccnt[row], c);
        __syncthreads();
        unsigned* dst = g_cand + (size_t)row * NNE + sbase;
        for (int i = tid; i < c; i += 256) dst[i] = st[i];
    }
}

// ---------------- K4: b16 sub-select, exact recompute ONLY on +-1-quantum mid set ----------------
__global__ void __launch_bounds__(1024) k_fin(float* __restrict__ out,
                                              const float* __restrict__ U,
                                              const float* __restrict__ D) {
    int row = blockIdx.x;
    int C = g_ccnt[row];
    if (C == 0) return;
    int tid = threadIdx.x;
    __shared__ unsigned h64[64];
    __shared__ unsigned h[2048];
    __shared__ unsigned ss[1024];
    __shared__ int r_bin, r_rem;
    __shared__ unsigned r_cnt;
    __shared__ int sAbove, midcnt, tie_cnt;
    __shared__ int sT16o, sNeedM;
    __shared__ unsigned tie_idx[TIE_CAP];

    unsigned thr = g_p1k[row], klo = g_klo[row];
    const unsigned* cw = g_cand + (size_t)row * NNE;
    uint2* cx = g_cand2 + (size_t)row * NNE;
    const float* Ur = U + (size_t)row * NNE;
    const float* Dr = D + (size_t)row * NNE;
    if (tid == 0) { sAbove = 0; midcnt = 0; tie_cnt = 0; }
    if (tid < 64) h64[tid] = 0u;
    h[tid] = 0u; h[tid + 1024] = 0u;
    __syncthreads();

    // pass A: b16 histogram (range <= 34 values, fits 64) + provisional-1 count
    int myA = 0;
    for (int i = tid; i < C; i += 1024) {
        unsigned b = cw[i] >> 16;
        if (b >= thr) myA++;
        unsigned off = b - klo;
        if (off > 63u) off = 63u;     // never fires (range <= 34 by construction)
        atomicAdd(&h64[off], 1u);
    }
    if (myA) atomicAdd(&sAbove, myA);
    __syncthreads();

    // select b16 value T16 containing rank 'need' (descending)
    if (tid == 0) {
        int need = g_rem[row] + sAbove;
        if (need > C) need = C;
        if (need < 1) need = 1;
        unsigned cum = 0;
        int T16o = 0, remT = 1;
        for (int o = 63; o >= 0; --o) {
            unsigned c = h64[o];
            if (cum + c >= (unsigned)need) { T16o = o; remT = need - (int)cum; break; }
            cum += c;
        }
        unsigned hUp = (T16o + 1 <= 63) ? h64[T16o + 1] : 0u;
        sT16o = T16o;
        sNeedM = remT + (int)hUp;     // rank within the +-1-quantum mid set
    }
    __syncthreads();
    int T16o = sT16o;

    // pass B: classify; >= +2 quanta -> 1, <= -2 quanta -> 0, else mid (exact key)
    for (int i = tid; i < C; i += 1024) {
        unsigned wd = cw[i];
        int off = (int)((wd >> 16) - klo);
        if (off > 63) off = 63;
        unsigned idx = wd & 0xFFFFu;
        if (off >= T16o + 2)      out[(size_t)row * NNE + idx] = 1.0f;
        else if (off <= T16o - 2) out[(size_t)row * NNE + idx] = 0.0f;
        else {
            int p = atomicAdd(&midcnt, 1);
            unsigned ke = weight_key_exact(Ur[idx], Dr[idx]);
            cx[p] = make_uint2(ke, idx);
        }
    }
    __syncthreads();
    int M = midcnt;
    int needM = sNeedM;
    if (needM > M) needM = M;
    if (needM < 1) needM = 1;

    // level 1 on mid set: exact key bits [31:21]
    for (int i = tid; i < M; i += 1024) atomicAdd(&h[cx[i].x >> 21], 1u);
    __syncthreads();
    select_bin<2048, 1024>(h, ss, needM, &r_bin, &r_rem, &r_cnt);
    __syncthreads();
    unsigned pA = (unsigned)r_bin;
    int rem = r_rem;
    __syncthreads();

    // level 2: bits [20:10]
    h[tid] = 0u; h[tid + 1024] = 0u;
    __syncthreads();
    for (int i = tid; i < M; i += 1024) {
        unsigned ke = cx[i].x;
        if ((ke >> 21) == pA) atomicAdd(&h[(ke >> 10) & 2047u], 1u);
    }
    __syncthreads();
    select_bin<2048, 1024>(h, ss, rem, &r_bin, &r_rem, &r_cnt);
    __syncthreads();
    unsigned pB = (unsigned)r_bin;
    rem = r_rem;
    unsigned pre22 = (pA << 11) | pB;
    __syncthreads();

    // level 3: bits [9:0]
    h[tid] = 0u;
    __syncthreads();
    for (int i = tid; i < M; i += 1024) {
        unsigned ke = cx[i].x;
        if ((ke >> 10) == pre22) atomicAdd(&h[ke & 1023u], 1u);
    }
    __syncthreads();
    select_bin<1024, 1024>(h, ss, rem, &r_bin, &r_rem, &r_cnt);
    __syncthreads();

    unsigned T = (pA << 21) | (pB << 10) | (unsigned)r_bin;
    int needT = r_rem;
    int cntT = (int)r_cnt;
    float* orow = out + (size_t)row * NNE;

    if (needT == cntT) {
        for (int i = tid; i < M; i += 1024) {
            uint2 cd = cx[i];
            orow[cd.y] = (cd.x >= T) ? 1.0f : 0.0f;   // overwrite ALL mid elements
        }
    } else {
        for (int i = tid; i < M; i += 1024) {
            uint2 cd = cx[i];
            if (cd.x > T) orow[cd.y] = 1.0f;
            else if (cd.x < T) orow[cd.y] = 0.0f;
            else {
                int p = atomicAdd(&tie_cnt, 1);
                if (p < TIE_CAP) tie_idx[p] = cd.y;
            }
        }
        __syncthreads();
        int tc = tie_cnt < TIE_CAP ? tie_cnt : TIE_CAP;
        // stable tie-break: lowest original index first (argsort stability)
        for (int i = tid; i < tc; i += 1024) {
            unsigned my = tie_idx[i];
            int rank = 0;
            for (int j = 0; j < tc; j++) rank += (tie_idx[j] < my);
            orow[my] = (rank < needT) ? 1.0f : 0.0f;
        }
    }
}

// ---------------- launch ----------------
extern "C" void kernel_launch(void* const* d_in, const int* in_sizes, int n_in,
                              void* d_out, int out_size) {
    // metadata order: batch (unused), t, U, D
    const float* t = (const float*)d_in[1];
    const float* U = (const float*)d_in[2];
    const float* D = (const float*)d_in[3];
    float* out = (float*)d_out;

    k_keys<<<dim3(KB_PER_ROW, BB), 512>>>(U, D);
    k_sel1<<<BB, 256>>>(t, out);
    k_scan<<<dim3(16, BB), 256>>>(out);
    k_fin<<<BB, 1024>>>(out, U, D);
}